// round 8
// baseline (speedup 1.0000x reference)
#include <cuda_runtime.h>
#include <cstdint>

// ---- problem constants ----
#define BATCH   1024
#define NNODES  100
#define KD      640      // key dim (5*128)
#define KD4     160      // key dim in float4
#define POOL    128
#define TOPK    4
#define PD      2304     // prompt dim
#define PD4     576

// ---- output layout (flat float32, reference return order) ----
#define OUT_RS  (BATCH*TOPK*PD)          // 9437184
#define OUT_SIM (OUT_RS + 1)             // 9437185
#define OUT_US  (OUT_SIM + BATCH*POOL)   // 9568257

// ---- roles: bids 0..127 keys, 128..639 work (2 rows each), 640 final ----
#define B_WORK0  128
#define B_FIN    640
#define NBLOCKS  641

// ---- device scratch ----
__device__ float g_keynorm[POOL * KD];
__device__ int   g_idx[BATCH * TOPK];
__device__ float g_partial[512];
__device__ int   g_keys;    // key blocks done (==128)
__device__ int   g_done;    // work blocks done (==512)

// ---- f32x2 packed-FMA helpers (sm_103a) ----
__device__ __forceinline__ void fma2(unsigned long long& acc,
                                     unsigned long long a,
                                     unsigned long long b) {
    asm("fma.rn.f32x2 %0, %1, %2, %0;" : "+l"(acc) : "l"(a), "l"(b));
}
__device__ __forceinline__ float unpack_sum(unsigned long long v) {
    float lo, hi;
    asm("mov.b64 {%0, %1}, %2;" : "=f"(lo), "=f"(hi) : "l"(v));
    return lo + hi;
}
__device__ __forceinline__ void waitge(volatile int* p, int tgt) {
    while (*p < tgt) __nanosleep(64);
}

// ============================================================
__global__ __launch_bounds__(640, 2)
void mega(const float4* __restrict__ x, const float4* __restrict__ pk,
          const float4* __restrict__ prompt, float* __restrict__ out) {
    __shared__ float  xs[2][644];      // normalized rows (padded)
    __shared__ float4 part[2][160];    // half-1 partial sums
    __shared__ float  wss[20];
    __shared__ float  sims[2][132];
    __shared__ float  wsum[2];
    __shared__ int    sidx[8];

    const int bid  = blockIdx.x;
    const int t    = threadIdx.x;
    const int w    = t >> 5, lane = t & 31;

    if (bid < B_WORK0) {
        // ================= key normalize (p = bid) =================
        const int p = bid;
        float4 v = make_float4(0.f, 0.f, 0.f, 0.f);
        float ss = 0.f;
        if (t < 160) {
            v = pk[(size_t)p * KD4 + t];
            ss = v.x*v.x + v.y*v.y + v.z*v.z + v.w*v.w;
        }
        #pragma unroll
        for (int o = 16; o; o >>= 1) ss += __shfl_xor_sync(0xffffffffu, ss, o);
        if (lane == 0 && w < 5) wss[w] = ss;
        __syncthreads();
        if (t < 160) {
            float tot = wss[0] + wss[1] + wss[2] + wss[3] + wss[4];
            tot = fmaxf(tot, 1e-12f);
            float rs = rsqrtf(tot);
            rs = rs * (1.5f - 0.5f * tot * rs * rs);   // NR refine
            float4* o4 = reinterpret_cast<float4*>(g_keynorm);
            o4[(size_t)p * KD4 + t] = make_float4(v.x*rs, v.y*rs, v.z*rs, v.w*rs);
        }
        __syncthreads();
        if (t == 0) { __threadfence(); atomicAdd(&g_keys, 1); }

    } else if (bid < B_FIN) {
        // ================= work block: 2 rows =================
        const int i  = bid - B_WORK0;
        const int rb = i * 2;

        // ---- phase 1: mean + L2 normalize 2 rows -> smem ----
        // thread = (half, row, col); each sums 50 nodes (k1 geometry).
        // Normalizing the SUM == normalizing the mean (scale invariance).
        {
            const int half = t / 320;          // node half
            const int rem  = t - half * 320;
            const int r    = rem / 160;        // row in block
            const int c    = rem - r * 160;    // float4 column
            const float4* xp = x + (size_t)(rb + r) * (NNODES * KD4)
                                 + (size_t)half * 50 * KD4 + c;
            float4 a = make_float4(0.f, 0.f, 0.f, 0.f);
            #pragma unroll 10
            for (int n = 0; n < 50; n++) {
                float4 v = xp[(size_t)n * KD4];
                a.x += v.x; a.y += v.y; a.z += v.z; a.w += v.w;
            }
            if (half == 1) part[r][c] = a;
            __syncthreads();
            float ss = 0.f;
            if (half == 0) {
                float4 b = part[r][c];
                a.x += b.x; a.y += b.y; a.z += b.z; a.w += b.w;
                ss = a.x*a.x + a.y*a.y + a.z*a.z + a.w*a.w;
            }
            #pragma unroll
            for (int o = 16; o; o >>= 1) ss += __shfl_xor_sync(0xffffffffu, ss, o);
            if (lane == 0 && w < 10) wss[w] = ss;   // warps 0-4 row0, 5-9 row1
            __syncthreads();
            if (half == 0) {
                const int wb = r * 5;
                float tot = wss[wb] + wss[wb+1] + wss[wb+2] + wss[wb+3] + wss[wb+4];
                tot = fmaxf(tot, 1e-12f);
                float rs = rsqrtf(tot);
                rs = rs * (1.5f - 0.5f * tot * rs * rs);
                xs[r][c*4+0] = a.x*rs; xs[r][c*4+1] = a.y*rs;
                xs[r][c*4+2] = a.z*rs; xs[r][c*4+3] = a.w*rs;
            }
        }

        // ---- phase 2: wait keys (wave-1 blocks, effectively free) ----
        if (t == 0) { waitge(&g_keys, POOL); __threadfence(); }
        __syncthreads();

        // ---- phase 3: GEMM 2 rows x 128 pools (keys via L2 LDG) ----
        // threads 0..511: pg = t>>4 owns pools pg*4..+3; ds = t&15.
        if (t < 512) {
            const int pg = t >> 4;
            const int ds = t & 15;
            const ulonglong2* kg = reinterpret_cast<const ulonglong2*>(g_keynorm);

            unsigned long long acc[4][2];      // [pool u][row r]
            #pragma unroll
            for (int u = 0; u < 4; u++) { acc[u][0] = 0ull; acc[u][1] = 0ull; }

            #pragma unroll
            for (int cc = 0; cc < 10; cc++) {
                ulonglong2 kv[4];
                #pragma unroll
                for (int u = 0; u < 4; u++)
                    kv[u] = kg[(size_t)(pg * 4 + u) * KD4 + cc * 16 + ds];
                #pragma unroll
                for (int r = 0; r < 2; r++) {
                    ulonglong2 xv = *reinterpret_cast<const ulonglong2*>(
                        &xs[r][cc * 64 + ds * 4]);
                    #pragma unroll
                    for (int u = 0; u < 4; u++) {
                        fma2(acc[u][r], xv.x, kv[u].x);
                        fma2(acc[u][r], xv.y, kv[u].y);
                    }
                }
            }
            #pragma unroll
            for (int u = 0; u < 4; u++) {
                #pragma unroll
                for (int r = 0; r < 2; r++) {
                    float v = unpack_sum(acc[u][r]);
                    #pragma unroll
                    for (int o = 8; o; o >>= 1)
                        v += __shfl_xor_sync(0xffffffffu, v, o);
                    if (ds == 0) sims[r][pg * 4 + u] = v;
                }
            }
        }
        __syncthreads();

        // ---- sim out: 2x128, threads 0..255 ----
        if (t < 256) {
            int rr = t >> 7, pp = t & 127;
            out[OUT_SIM + (size_t)(rb + rr) * POOL + pp] = sims[rr][pp];
        }

        // ---- phase 4: top-4 (warps 0..1 -> rows 0..1) ----
        // monotone-bits composite key, smallest index on ties (jax.lax.top_k)
        if (w < 2) {
            float vals[4];
            #pragma unroll
            for (int s = 0; s < 4; s++) vals[s] = sims[w][lane + 32*s];
            float vsum = 0.f;
            #pragma unroll
            for (int k = 0; k < TOPK; k++) {
                unsigned long long best = 0ull;
                #pragma unroll
                for (int s = 0; s < 4; s++) {
                    unsigned u = __float_as_uint(vals[s]);
                    u = (u & 0x80000000u) ? ~u : (u | 0x80000000u);
                    unsigned long long comp =
                        ((unsigned long long)u << 32) | (127u - (lane + 32u*s));
                    if (comp > best) best = comp;
                }
                #pragma unroll
                for (int o = 16; o; o >>= 1) {
                    unsigned long long other = __shfl_xor_sync(0xffffffffu, best, o);
                    if (other > best) best = other;
                }
                unsigned pool = 127u - (unsigned)(best & 0xffffffffu);
                unsigned ub = (unsigned)(best >> 32);
                unsigned orig = (ub & 0x80000000u) ? (ub ^ 0x80000000u) : ~ub;
                vsum += __uint_as_float(orig);
                if (lane == (int)(pool & 31u)) vals[pool >> 5] = -1e30f;
                if (lane == 0) {
                    g_idx[(rb + w) * TOPK + k] = (int)pool;
                    sidx[w * 4 + k] = (int)pool;
                }
            }
            if (lane == 0) wsum[w] = vsum;
        }
        __syncthreads();

        // ---- phase 5: in-block gather: 8 segments x 576 f4 = 4608 ----
        float4* outbp = reinterpret_cast<float4*>(out);
        {
            const int obase = rb * 4 * PD4;
            #pragma unroll
            for (int s0 = 0; s0 < 4; s0 += 4) {   // j = 0..3 (2560)
                float4 v[4]; int di[4];
                #pragma unroll
                for (int k = 0; k < 4; k++) {
                    int idx = t + 640 * k;
                    int seg = idx / PD4;
                    int off = idx - seg * PD4;
                    v[k]  = prompt[(size_t)sidx[seg] * PD4 + off];
                    di[k] = obase + idx;
                }
                #pragma unroll
                for (int k = 0; k < 4; k++) outbp[di[k]] = v[k];
            }
            {   // j = 4..6 (1920 -> 4480)
                float4 v[3]; int di[3];
                #pragma unroll
                for (int k = 0; k < 3; k++) {
                    int idx = t + 640 * (4 + k);
                    int seg = idx / PD4;
                    int off = idx - seg * PD4;
                    v[k]  = prompt[(size_t)sidx[seg] * PD4 + off];
                    di[k] = obase + idx;
                }
                #pragma unroll
                for (int k = 0; k < 3; k++) outbp[di[k]] = v[k];
            }
            if (t < 128) {  // tail 4480..4607
                int idx = t + 4480;
                int seg = idx / PD4;
                int off = idx - seg * PD4;
                outbp[obase + idx] = prompt[(size_t)sidx[seg] * PD4 + off];
            }
        }

        if (t == 0) g_partial[i] = wsum[0] + wsum[1];   // fixed order
        __syncthreads();
        __threadfence();   // make g_idx/g_partial visible before done-signal
        if (t == 0) atomicAdd(&g_done, 1);

    } else {
        // ================= final: reduce_sim + usage + reset =================
        __shared__ float red[512];
        __shared__ int   histo[128];
        if (t == 0) { waitge(&g_done, 512); __threadfence(); }
        __syncthreads();
        if (t < 512) red[t] = g_partial[t];
        if (t < 128) histo[t] = 0;
        __syncthreads();
        #pragma unroll
        for (int o = 256; o; o >>= 1) {
            if (t < o && t + o < 512) red[t] += red[t + o];
            __syncthreads();
        }
        if (t == 0) out[OUT_RS] = red[0] * (1.0f / (float)BATCH);
        if (t < 512) {
            #pragma unroll
            for (int j = 0; j < 8; j++)
                atomicAdd(&histo[g_idx[t * 8 + j]], 1);
        }
        __syncthreads();
        if (t < 128) out[OUT_US + t] = (float)histo[t];
        // reset flags for next graph replay (all waiters already passed)
        if (t == 0) { g_keys = 0; g_done = 0; }
    }
}

// ============================================================
extern "C" void kernel_launch(void* const* d_in, const int* in_sizes, int n_in,
                              void* d_out, int out_size) {
    const float* x      = (const float*)d_in[0];  // [1024, 100, 640]
    const float* prompt = (const float*)d_in[1];  // [128, 1, 2304]
    const float* pkey   = (const float*)d_in[2];  // [128, 640]
    float* out = (float*)d_out;

    mega<<<NBLOCKS, 640>>>(reinterpret_cast<const float4*>(x),
                           reinterpret_cast<const float4*>(pkey),
                           reinterpret_cast<const float4*>(prompt), out);
}